// round 12
// baseline (speedup 1.0000x reference)
#include <cuda_runtime.h>
#include <stdint.h>

#define NPTS  256
#define DIM   256
#define KNN   16
#define NB    128       // 2 rows/block, 512 threads (h=0/1 halves), independent blocks
#define EPSV  1e-12f
#define CHUNK 64        // dims staged per tile chunk
#define NCH   (DIM / CHUNK)           // 4
#define TPAD  68        // tile row stride (floats): 64 + 4 pad -> conflict-free
#define TILEF (NPTS * TPAD)           // floats per tile buffer
#define SMEM_DYN (2 * TILEF * 4)      // two tile buffers (bytes) = 139264

__device__ float    g_part[NB];
__device__ unsigned g_done = 0;
typedef unsigned long long u64;

#define FMA2(acc, x, y) asm("fma.rn.f32x2 %0, %1, %2, %0;" : "+l"(acc) : "l"(x), "l"(y))
#define ADD2(a, b)      asm("add.rn.f32x2 %0, %0, %1;"     : "+l"(a)   : "l"(b))
#define CPA16(dst, src) asm volatile("cp.async.cg.shared.global [%0], [%1], 16;" :: "r"(dst), "l"(src))
#define CPA_COMMIT()    asm volatile("cp.async.commit_group;")
#define CPA_WAIT0()     asm volatile("cp.async.wait_group 0;" ::: "memory")

__global__ __launch_bounds__(512, 1)
void k_fused(const float* __restrict__ yi, const float* __restrict__ yit,
             float* __restrict__ out) {
    extern __shared__ __align__(16) float dynsmem[];      // 2 tile buffers
    __shared__ __align__(16) float s_n[2][DIM];           // normalized yi rows
    __shared__ __align__(16) float s_t[2][DIM];           // normalized yit rows
    __shared__ unsigned sk[2][NPTS];
    __shared__ float    red0[16], red1[16], red2[16];
    __shared__ float4   sh_par[2];   // ia, ic, rn, rt per row
    __shared__ float    sh_ds[2];    // dself per row
    __shared__ float    shred[16];
    __shared__ unsigned s_last;

    const int t   = threadIdx.x, b = blockIdx.x;
    const int h   = t >> 8;          // which row of the pair this half handles
    const int col = t & 255;
    const int w   = t >> 5, l = t & 31;
    const int row = 2 * b + h;

    // ---------------- Phase A: normalize row `row` (3 sums, one reduction) ----------------
    float a = yi [row * DIM + col];
    float c = yit[row * DIM + col];
    float paa = a * a, pcc = c * c, pac = a * c;
    #pragma unroll
    for (int o = 16; o; o >>= 1) {
        paa += __shfl_down_sync(0xffffffffu, paa, o);
        pcc += __shfl_down_sync(0xffffffffu, pcc, o);
        pac += __shfl_down_sync(0xffffffffu, pac, o);
    }
    if (l == 0) { red0[w] = paa; red1[w] = pcc; red2[w] = pac; }
    __syncthreads();
    if (t == h * 256) {              // one thread per half
        float sa = 0.f, sc = 0.f, sac = 0.f;
        #pragma unroll
        for (int m = 0; m < 8; m++) {
            sa  += red0[h * 8 + m];
            sc  += red1[h * 8 + m];
            sac += red2[h * 8 + m];
        }
        float ia = 1.0f / sqrtf(sa + EPSV);
        float ic = 1.0f / sqrtf(sc + EPSV);
        float rn = sa * ia * ia, rt = sc * ic * ic;
        sh_par[h] = make_float4(ia, ic, rn, rt);
        sh_ds[h]  = 0.5f * sqrtf(fmaxf(rn + rt - 2.f * ia * ic * sac, 0.f) + EPSV);
    }
    __syncthreads();
    float4 P = sh_par[h];            // ia, ic, rn, rt of this half's row
    s_n[h][col] = a * P.x;
    s_t[h][col] = c * P.y;
    // (ordered before first compute by the prologue barrier below)

    // ---------------- Phase B: cp.async double-buffered staged dual dot ----------------
    const float4* yi4 = (const float4*)yi;
    const ulonglong2* pn = (const ulonglong2*)s_n[h];
    const ulonglong2* pc = (const ulonglong2*)s_t[h];

    // staging geometry: 4096 float4 slots per chunk, 8 per thread
    // lin = i*512 + t; r = lin>>4 (16 float4/row), k = lin&15
    const int rA = t >> 4, kA = t & 15;           // rows advance by 32 per i
    unsigned sbase0 = (unsigned)__cvta_generic_to_shared(dynsmem);
    unsigned sbase1 = sbase0 + TILEF * 4;
    const float* gbase = yi + rA * DIM + kA * 4;  // + i*32*DIM + ch*CHUNK
    const unsigned soff = rA * TPAD * 4 + kA * 16;

    u64 dnx = 0, dny = 0, dtx = 0, dty = 0, ssx = 0, ssy = 0;

    // prologue: stage chunk 0 into buffer 0
    #pragma unroll
    for (int i = 0; i < 8; i++)
        CPA16(sbase0 + soff + i * 32 * TPAD * 4, gbase + i * 32 * DIM);
    CPA_COMMIT();
    CPA_WAIT0();
    __syncthreads();

    #pragma unroll
    for (int ch = 0; ch < NCH; ch++) {
        const unsigned curb = (ch & 1) ? sbase1 : sbase0;
        // issue next chunk's copies into the other buffer (no registers consumed)
        if (ch + 1 < NCH) {
            const unsigned nxtb = (ch & 1) ? sbase0 : sbase1;
            #pragma unroll
            for (int i = 0; i < 8; i++)
                CPA16(nxtb + soff + i * 32 * TPAD * 4,
                      gbase + i * 32 * DIM + (ch + 1) * CHUNK);
            CPA_COMMIT();
        }

        // compute from current buffer: column `col` dims ch*64 .. ch*64+63
        const ulonglong2* tl =
            (const ulonglong2*)(dynsmem + (ch & 1) * TILEF + col * TPAD);
        #pragma unroll
        for (int q = 0; q < 16; q++) {
            ulonglong2 v = tl[q];                  // conflict-free LDS.128
            ulonglong2 A = pn[ch * 16 + q];        // warp-uniform broadcast
            ulonglong2 C = pc[ch * 16 + q];
            FMA2(dnx, A.x, v.x);  FMA2(dny, A.y, v.y);
            FMA2(dtx, C.x, v.x);  FMA2(dty, C.y, v.y);
            FMA2(ssx, v.x, v.x);  FMA2(ssy, v.y, v.y);
        }

        if (ch + 1 < NCH) CPA_WAIT0();   // next chunk's data arrived (this thread)
        __syncthreads();                  // all threads' copies visible; cur buffer free
    }

    ADD2(dnx, dny);  ADD2(dtx, dty);  ADD2(ssx, ssy);
    float nlo, nhi, tlo, thi, slo, shi;
    asm("mov.b64 {%0, %1}, %2;" : "=f"(nlo), "=f"(nhi) : "l"(dnx));
    asm("mov.b64 {%0, %1}, %2;" : "=f"(tlo), "=f"(thi) : "l"(dtx));
    asm("mov.b64 {%0, %1}, %2;" : "=f"(slo), "=f"(shi) : "l"(ssx));

    float ss  = slo + shi;
    float iac = 1.0f / sqrtf(ss + EPSV);
    float rnt = ss * iac * iac;
    float d1  = 0.5f * sqrtf(fmaxf(P.z + rnt - 2.f * ((nlo + nhi) * iac), 0.f) + EPSV);
    float d2  = 0.5f * sqrtf(fmaxf(P.w + rnt - 2.f * ((tlo + thi) * iac), 0.f) + EPSV);

    unsigned key = __float_as_uint(d1);   // positive: bit order == value order
    sk[h][col] = key;
    __syncthreads();

    // ---------------- Parallel rank-count selection ----------------
    // Self distance is the row minimum; ranks 1..16 = K neighbors, rank 1 = second_nn.
    int rc = 0;
    const uint4* qk = (const uint4*)sk[h];
    #pragma unroll 8
    for (int q = 0; q < NPTS / 4; q++) {
        uint4 v = qk[q];                       // broadcast LDS.128
        rc += (v.x < key) + (v.y < key) + (v.z < key) + (v.w < key);
    }

    float contrib = 0.f;
    if (rc >= 1 && rc <= KNN) {
        float df = d1 - d2;
        contrib = df * df;
        if (rc == 1) contrib += fmaxf(sh_ds[h] + 0.6f - d1, 0.f);
    }

    #pragma unroll
    for (int o = 16; o; o >>= 1) contrib += __shfl_down_sync(0xffffffffu, contrib, o);
    if (l == 0) shred[w] = contrib;
    __syncthreads();
    if (t == 0) {
        float s = 0.f;
        #pragma unroll
        for (int m = 0; m < 16; m++) s += shred[m];
        g_part[b] = s - 2.0f * (float)KNN * 0.0025f;   // both rows' -K*T
    }

    // ---------------- last arriving block: deterministic final reduce ----------------
    __threadfence();
    __syncthreads();
    if (t == 0) s_last = atomicAdd(&g_done, 1);
    __syncthreads();
    if (s_last == NB - 1) {
        float v = (t < NB) ? *((volatile float*)&g_part[t]) : 0.f;
        #pragma unroll
        for (int o = 16; o; o >>= 1) v += __shfl_down_sync(0xffffffffu, v, o);
        if (l == 0) shred[w] = v;
        __syncthreads();
        if (t == 0) {
            float s = 0.f;
            #pragma unroll
            for (int m = 0; m < 16; m++) s += shred[m];
            out[0] = s;
            *((volatile unsigned*)&g_done) = 0;   // reset for next graph replay
        }
    }
}

extern "C" void kernel_launch(void* const* d_in, const int* in_sizes, int n_in,
                              void* d_out, int out_size) {
    const float* yi  = (const float*)d_in[0];
    const float* yit = (const float*)d_in[1];
    // idempotent; host-side attribute set (not a stream op, capture-safe)
    cudaFuncSetAttribute(k_fused, cudaFuncAttributeMaxDynamicSharedMemorySize, SMEM_DYN);
    k_fused<<<NB, 512, SMEM_DYN>>>(yi, yit, (float*)d_out);
}

// round 14
// speedup vs baseline: 1.1196x; 1.1196x over previous
#include <cuda_runtime.h>
#include <stdint.h>

#define NPTS  256
#define DIM   256
#define KNN   16
#define NB    128       // 2 rows/block, 512 threads (h=0/1 halves), independent blocks
#define EPSV  1e-12f
#define CHUNK 32        // dims staged per tile
#define NCH   (DIM / CHUNK)
#define TPAD  36        // tile row stride (floats): conflict-free LDS.128 phases

__device__ float    g_part[NB];
__device__ unsigned g_done = 0;
typedef unsigned long long u64;

#define FMA2(acc, x, y) asm("fma.rn.f32x2 %0, %1, %2, %0;" : "+l"(acc) : "l"(x), "l"(y))
#define ADD2(a, b)      asm("add.rn.f32x2 %0, %0, %1;"     : "+l"(a)   : "l"(b))

__device__ __forceinline__ unsigned warp_min_u32(unsigned v) {
    #pragma unroll
    for (int o = 16; o; o >>= 1) {
        unsigned u = __shfl_xor_sync(0xffffffffu, v, o);
        v = u < v ? u : v;
    }
    return v;
}

__global__ __launch_bounds__(512, 1)
void k_fused(const float* __restrict__ yi, const float* __restrict__ yit,
             float* __restrict__ out) {
    __shared__ __align__(16) float s_tile[NPTS * TPAD];          // 36 KB
    __shared__ __align__(16) float s_n[2][DIM];                  // normalized yi rows
    __shared__ __align__(16) float s_t[2][DIM];                  // normalized yit rows
    __shared__ unsigned s_cand[2][NPTS];   // compacted candidate keys per half
    __shared__ unsigned s_w3[16];          // per-warp 3rd-smallest
    __shared__ int      s_cnt[2];          // candidate counters
    __shared__ float    red0[16], red1[16], red2[16];
    __shared__ float4   sh_par[2];   // ia, ic, rn, rt per row
    __shared__ float    sh_ds[2];    // dself per row
    __shared__ float    shred[16];
    __shared__ unsigned s_last;

    const int t   = threadIdx.x, b = blockIdx.x;
    const int h   = t >> 8;          // which row of the pair this half handles
    const int col = t & 255;
    const int w   = t >> 5, l = t & 31;
    const int row = 2 * b + h;

    if (t < 2) s_cnt[t] = 0;         // covered by Phase A's first barrier

    // ---------------- Phase A: normalize row `row` (3 sums, one reduction) ----------------
    float a = yi [row * DIM + col];
    float c = yit[row * DIM + col];
    float paa = a * a, pcc = c * c, pac = a * c;
    #pragma unroll
    for (int o = 16; o; o >>= 1) {
        paa += __shfl_down_sync(0xffffffffu, paa, o);
        pcc += __shfl_down_sync(0xffffffffu, pcc, o);
        pac += __shfl_down_sync(0xffffffffu, pac, o);
    }
    if (l == 0) { red0[w] = paa; red1[w] = pcc; red2[w] = pac; }
    __syncthreads();
    if (t == h * 256) {              // one thread per half
        float sa = 0.f, sc = 0.f, sac = 0.f;
        #pragma unroll
        for (int m = 0; m < 8; m++) {
            sa  += red0[h * 8 + m];
            sc  += red1[h * 8 + m];
            sac += red2[h * 8 + m];
        }
        float ia = 1.0f / sqrtf(sa + EPSV);
        float ic = 1.0f / sqrtf(sc + EPSV);
        float rn = sa * ia * ia, rt = sc * ic * ic;
        sh_par[h] = make_float4(ia, ic, rn, rt);
        sh_ds[h]  = 0.5f * sqrtf(fmaxf(rn + rt - 2.f * ia * ic * sac, 0.f) + EPSV);
    }
    __syncthreads();
    float4 P = sh_par[h];            // ia, ic, rn, rt of this half's row
    s_n[h][col] = a * P.x;
    s_t[h][col] = c * P.y;
    // (ordered before first compute by the staging barrier below)

    // ---------------- Phase B: staged fused norm + dual dot, register prefetch ----------------
    const float4* yi4 = (const float4*)yi;
    const ulonglong2* pn = (const ulonglong2*)s_n[h];
    const ulonglong2* pc = (const ulonglong2*)s_t[h];

    const int lin0 = t,        r0i = lin0 >> 3, k0i = lin0 & 7;
    const int lin1 = 512 + t,  r1i = lin1 >> 3, k1i = lin1 & 7;
    const int lin2 = 1024 + t, r2i = lin2 >> 3, k2i = lin2 & 7;
    const int lin3 = 1536 + t, r3i = lin3 >> 3, k3i = lin3 & 7;
    const float4* gp0 = yi4 + r0i * (DIM / 4) + k0i;
    const float4* gp1 = yi4 + r1i * (DIM / 4) + k1i;
    const float4* gp2 = yi4 + r2i * (DIM / 4) + k2i;
    const float4* gp3 = yi4 + r3i * (DIM / 4) + k3i;
    float* sp0 = &s_tile[r0i * TPAD + 4 * k0i];
    float* sp1 = &s_tile[r1i * TPAD + 4 * k1i];
    float* sp2 = &s_tile[r2i * TPAD + 4 * k2i];
    float* sp3 = &s_tile[r3i * TPAD + 4 * k3i];

    u64 dnx = 0, dny = 0, dtx = 0, dty = 0, ssx = 0, ssy = 0;
    const ulonglong2* tl = (const ulonglong2*)&s_tile[col * TPAD];

    float4 pf0 = gp0[0], pf1 = gp1[0], pf2 = gp2[0], pf3 = gp3[0];

    #pragma unroll
    for (int ch = 0; ch < NCH; ch++) {
        *(float4*)sp0 = pf0;  *(float4*)sp1 = pf1;
        *(float4*)sp2 = pf2;  *(float4*)sp3 = pf3;
        __syncthreads();
        if (ch + 1 < NCH) {
            pf0 = gp0[(ch + 1) * 8];  pf1 = gp1[(ch + 1) * 8];
            pf2 = gp2[(ch + 1) * 8];  pf3 = gp3[(ch + 1) * 8];
        }
        #pragma unroll
        for (int q = 0; q < 8; q++) {
            ulonglong2 v = tl[q];                // column `col` dims, conflict-free
            ulonglong2 A = pn[ch * 8 + q];       // warp-uniform -> LDS broadcast
            ulonglong2 C = pc[ch * 8 + q];
            FMA2(dnx, A.x, v.x);  FMA2(dny, A.y, v.y);
            FMA2(dtx, C.x, v.x);  FMA2(dty, C.y, v.y);
            FMA2(ssx, v.x, v.x);  FMA2(ssy, v.y, v.y);
        }
        __syncthreads();
    }

    ADD2(dnx, dny);  ADD2(dtx, dty);  ADD2(ssx, ssy);
    float nlo, nhi, tlo, thi, slo, shi;
    asm("mov.b64 {%0, %1}, %2;" : "=f"(nlo), "=f"(nhi) : "l"(dnx));
    asm("mov.b64 {%0, %1}, %2;" : "=f"(tlo), "=f"(thi) : "l"(dtx));
    asm("mov.b64 {%0, %1}, %2;" : "=f"(slo), "=f"(shi) : "l"(ssx));

    float ss  = slo + shi;
    float iac = 1.0f / sqrtf(ss + EPSV);
    float rnt = ss * iac * iac;
    float d1  = 0.5f * sqrtf(fmaxf(P.z + rnt - 2.f * ((nlo + nhi) * iac), 0.f) + EPSV);
    float d2  = 0.5f * sqrtf(fmaxf(P.w + rnt - 2.f * ((tlo + thi) * iac), 0.f) + EPSV);

    unsigned key = __float_as_uint(d1);   // positive: bit order == value order

    // ---------------- Pruned exact rank-count selection ----------------
    // T = max over this half's 8 warps of (warp 3rd-smallest key).
    // >=24 keys <= T, so any key >= T has rank >= 23 > KNN (irrelevant).
    // For key < T: all smaller keys are also < T, so rank among the
    // candidate set equals the exact global rank.
    {
        unsigned kk = key;
        unsigned m1 = warp_min_u32(kk); if (kk == m1) kk = 0xffffffffu;
        unsigned m2 = warp_min_u32(kk); if (kk == m2) kk = 0xffffffffu;
        unsigned m3 = warp_min_u32(kk);
        if (l == 0) s_w3[w] = m3;
    }
    __syncthreads();
    unsigned T = 0;
    #pragma unroll
    for (int m = 0; m < 8; m++) {
        unsigned v = s_w3[h * 8 + m];
        T = v > T ? v : T;
    }

    bool cand = key < T;
    unsigned cmask = __ballot_sync(0xffffffffu, cand);
    int wcnt = __popc(cmask);
    int base = 0;
    if (l == 0 && wcnt) base = atomicAdd(&s_cnt[h], wcnt);
    base = __shfl_sync(0xffffffffu, base, 0);
    if (cand) s_cand[h][base + __popc(cmask & ((1u << l) - 1u))] = key;
    __syncthreads();

    int rc = 999;
    if (cand) {
        rc = 0;
        const int n = s_cnt[h];
        const unsigned* cl = s_cand[h];
        for (int j = 0; j < n; j++) rc += (cl[j] < key);
    }

    float contrib = 0.f;
    if (rc >= 1 && rc <= KNN) {
        float df = d1 - d2;
        contrib = df * df;
        if (rc == 1) contrib += fmaxf(sh_ds[h] + 0.6f - d1, 0.f);
    }

    #pragma unroll
    for (int o = 16; o; o >>= 1) contrib += __shfl_down_sync(0xffffffffu, contrib, o);
    if (l == 0) shred[w] = contrib;
    __syncthreads();
    if (t == 0) {
        float s = 0.f;
        #pragma unroll
        for (int m = 0; m < 16; m++) s += shred[m];
        g_part[b] = s - 2.0f * (float)KNN * 0.0025f;   // both rows' -K*T
    }

    // ---------------- last arriving block: deterministic final reduce ----------------
    __threadfence();
    __syncthreads();
    if (t == 0) s_last = atomicAdd(&g_done, 1);
    __syncthreads();
    if (s_last == NB - 1) {
        float v = (t < NB) ? *((volatile float*)&g_part[t]) : 0.f;
        #pragma unroll
        for (int o = 16; o; o >>= 1) v += __shfl_down_sync(0xffffffffu, v, o);
        if (l == 0) shred[w] = v;
        __syncthreads();
        if (t == 0) {
            float s = 0.f;
            #pragma unroll
            for (int m = 0; m < 16; m++) s += shred[m];
            out[0] = s;
            *((volatile unsigned*)&g_done) = 0;   // reset for next graph replay
        }
    }
}

extern "C" void kernel_launch(void* const* d_in, const int* in_sizes, int n_in,
                              void* d_out, int out_size) {
    const float* yi  = (const float*)d_in[0];
    const float* yit = (const float*)d_in[1];
    k_fused<<<NB, 512>>>(yi, yit, (float*)d_out);
}